// round 1
// baseline (speedup 1.0000x reference)
#include <cuda_runtime.h>
#include <cstdint>

typedef unsigned long long ull;

#define B_ 16
#define S_ 16384
#define C_ 256
#define NH_ 8
#define VD_ 64
#define NBLK_PER_B 8
#define ROWS_PER_BLK (S_ / NBLK_PER_B)               /* 2048 */
#define NWARPS 8
#define QUADS_PER_WARP (ROWS_PER_BLK / 4 / NWARPS)   /* 64   */
#define NPART (B_ * NBLK_PER_B * NWARPS)             /* 1024 */
#define PART_STRIDE 2064                             /* 2048 acc + 8 sums + pad */

// Device-global scratch (no runtime allocation allowed).
__device__ __align__(16) float g_wqT[NH_ * C_];                 // wq transposed: [h][c]
__device__ __align__(16) float g_part[(size_t)NPART * PART_STRIDE];

// ---------------- packed f32x2 helpers ----------------
__device__ __forceinline__ ull f2fma(ull a, ull b, ull c) {
    ull d; asm("fma.rn.f32x2 %0,%1,%2,%3;" : "=l"(d) : "l"(a), "l"(b), "l"(c)); return d;
}
__device__ __forceinline__ ull f2mul(ull a, ull b) {
    ull d; asm("mul.rn.f32x2 %0,%1,%2;" : "=l"(d) : "l"(a), "l"(b)); return d;
}
__device__ __forceinline__ ull f2add(ull a, ull b) {
    ull d; asm("add.rn.f32x2 %0,%1,%2;" : "=l"(d) : "l"(a), "l"(b)); return d;
}
__device__ __forceinline__ ull pk(float x, float y) {
    ull r; asm("mov.b64 %0,{%1,%2};" : "=l"(r) : "f"(x), "f"(y)); return r;
}
__device__ __forceinline__ float2 upk(ull v) {
    float2 r; asm("mov.b64 {%0,%1},%2;" : "=f"(r.x), "=f"(r.y) : "l"(v)); return r;
}
__device__ __forceinline__ ull shx64(ull v, int m) {
    unsigned lo, hi;
    asm("mov.b64 {%0,%1},%2;" : "=r"(lo), "=r"(hi) : "l"(v));
    lo = __shfl_xor_sync(0xffffffffu, lo, m);
    hi = __shfl_xor_sync(0xffffffffu, hi, m);
    ull r; asm("mov.b64 %0,{%1,%2};" : "=l"(r) : "r"(lo), "r"(hi)); return r;
}
__device__ __forceinline__ ull shidx64(ull v, int src) {
    unsigned lo, hi;
    asm("mov.b64 {%0,%1},%2;" : "=r"(lo), "=r"(hi) : "l"(v));
    lo = __shfl_sync(0xffffffffu, lo, src);
    hi = __shfl_sync(0xffffffffu, hi, src);
    ull r; asm("mov.b64 %0,{%1,%2};" : "=l"(r) : "r"(lo), "r"(hi)); return r;
}

// Value-halving warp reduction: 8 packed f32x2 values summed over 32 lanes.
// Afterwards, lane l holds the full-warp sum of value index h(l) = (l>>2)&7.
__device__ __forceinline__ ull reduce8(ull v[8], int lane) {
    {
        bool hi = (lane & 16) != 0;
#pragma unroll
        for (int j = 0; j < 4; j++) {
            ull snd = hi ? v[j] : v[j + 4];
            ull kp  = hi ? v[j + 4] : v[j];
            v[j] = f2add(kp, shx64(snd, 16));
        }
    }
    {
        bool hi = (lane & 8) != 0;
#pragma unroll
        for (int j = 0; j < 2; j++) {
            ull snd = hi ? v[j] : v[j + 2];
            ull kp  = hi ? v[j + 2] : v[j];
            v[j] = f2add(kp, shx64(snd, 8));
        }
    }
    {
        bool hi = (lane & 4) != 0;
        ull snd = hi ? v[0] : v[1];
        ull kp  = hi ? v[1] : v[0];
        v[0] = f2add(kp, shx64(snd, 4));
    }
    v[0] = f2add(v[0], shx64(v[0], 2));
    v[0] = f2add(v[0], shx64(v[0], 1));
    return v[0];
}

// ---------------- Kernel A: fold Wk @ query -> wq[h][c] ----------------
__global__ void mha_prep(const float* __restrict__ Wk, const float* __restrict__ q) {
    int h = blockIdx.x;        // 0..7
    int c = threadIdx.x;       // 0..255
    float a = 0.f;
#pragma unroll 8
    for (int d = 0; d < 64; d++)
        a += Wk[c * 512 + h * 64 + d] * q[h * 64 + d];
    g_wqT[h * C_ + c] = a;
}

// ---------------- Kernel B: fused scores + exp + weighted kv accumulation ----------------
__global__ void __launch_bounds__(256, 1) mha_main(const float* __restrict__ kv) {
    const int b  = blockIdx.x / NBLK_PER_B;
    const int cb = blockIdx.x % NBLK_PER_B;
    const int w    = threadIdx.x >> 5;
    const int lane = threadIdx.x & 31;
    const int c0   = lane * 8;   // this lane owns c in [c0, c0+8)

    // wq packs: wq2[j2][h] = (wq[c0+2*j2][h], wq[c0+2*j2+1][h])  (64 regs, loop-invariant)
    ull wq2[4][NH_];
#pragma unroll
    for (int j2 = 0; j2 < 4; j2++)
#pragma unroll
        for (int h = 0; h < NH_; h++)
            wq2[j2][h] = *reinterpret_cast<const ull*>(g_wqT + h * C_ + c0 + 2 * j2);

    ull acc2[NH_][4];
#pragma unroll
    for (int h = 0; h < NH_; h++)
#pragma unroll
        for (int j2 = 0; j2 < 4; j2++) acc2[h][j2] = 0ull;
    ull sum2 = 0ull;  // per-lane packed weight sum for head (lane>>2)&7

    const float* base = kv + ((size_t)b * S_ + (size_t)cb * ROWS_PER_BLK) * C_;

    for (int i = 0; i < QUADS_PER_WARP; i++) {
        const int r = 4 * (w + NWARPS * i);  // row quad start within chunk

        // Load 4 rows x 32B/lane up front (MLP=8 LDG.128 per warp iteration).
        ull kvp[4][4];
#pragma unroll
        for (int rr = 0; rr < 4; rr++) {
            const float* rowp = base + (size_t)(r + rr) * C_ + c0;
            ulonglong2 a0 = *reinterpret_cast<const ulonglong2*>(rowp);
            ulonglong2 a1 = *reinterpret_cast<const ulonglong2*>(rowp + 4);
            kvp[rr][0] = a0.x; kvp[rr][1] = a0.y;
            kvp[rr][2] = a1.x; kvp[rr][3] = a1.y;
        }

        // Per-row 8-head score partials (packed over c-pairs), then horizontal add.
        float s[4][NH_];
#pragma unroll
        for (int rr = 0; rr < 4; rr++) {
            ull p[NH_];
#pragma unroll
            for (int h = 0; h < NH_; h++) p[h] = f2mul(kvp[rr][0], wq2[0][h]);
#pragma unroll
            for (int j2 = 1; j2 < 4; j2++)
#pragma unroll
                for (int h = 0; h < NH_; h++) p[h] = f2fma(kvp[rr][j2], wq2[j2][h], p[h]);
#pragma unroll
            for (int h = 0; h < NH_; h++) { float2 t = upk(p[h]); s[rr][h] = t.x + t.y; }
        }

        // Pack row-pairs so one reduction serves two rows.
        ull v0[NH_], v1[NH_];
#pragma unroll
        for (int h = 0; h < NH_; h++) { v0[h] = pk(s[0][h], s[1][h]); v1[h] = pk(s[2][h], s[3][h]); }
        ull r0 = reduce8(v0, lane);  // lane holds packed (score_row0, score_row1) of head (lane>>2)&7
        ull r1 = reduce8(v1, lane);

        // exp (scores are O(1); no max subtraction needed in fp32)
        float2 e0 = upk(r0), e1 = upk(r1);
        e0.x = __expf(e0.x); e0.y = __expf(e0.y);
        e1.x = __expf(e1.x); e1.y = __expf(e1.y);
        ull w0 = pk(e0.x, e0.y), w1 = pk(e1.x, e1.y);
        sum2 = f2add(sum2, f2add(w0, w1));

        // Broadcast weights per head and accumulate packed kv.
#pragma unroll
        for (int h = 0; h < NH_; h++) {
            ull wp0 = shidx64(w0, 4 * h);
            ull wp1 = shidx64(w1, 4 * h);
            float2 t0 = upk(wp0), t1 = upk(wp1);
            ull a0 = pk(t0.x, t0.x), a1 = pk(t0.y, t0.y);
            ull a2 = pk(t1.x, t1.x), a3 = pk(t1.y, t1.y);
#pragma unroll
            for (int j2 = 0; j2 < 4; j2++) {
                ull a = acc2[h][j2];
                a = f2fma(a0, kvp[0][j2], a);
                a = f2fma(a1, kvp[1][j2], a);
                a = f2fma(a2, kvp[2][j2], a);
                a = f2fma(a3, kvp[3][j2], a);
                acc2[h][j2] = a;
            }
        }
    }

    // Write warp partials.
    const int gw = blockIdx.x * NWARPS + w;
    float* dst = g_part + (size_t)gw * PART_STRIDE;
#pragma unroll
    for (int h = 0; h < NH_; h++)
#pragma unroll
        for (int j2 = 0; j2 < 4; j2++)
            *reinterpret_cast<ull*>(dst + h * C_ + c0 + 2 * j2) = acc2[h][j2];
    if ((lane & 3) == 0) {
        float2 sv = upk(sum2);
        dst[2048 + (lane >> 2)] = sv.x + sv.y;
    }
}

// ---------------- Kernel C: merge partials, normalize, project with Wv ----------------
__global__ void mha_combine(const float* __restrict__ Wv, const float* __restrict__ bv,
                            float* __restrict__ out) {
    const int b = blockIdx.x >> 3;
    const int h = blockIdx.x & 7;
    const int t = threadIdx.x;  // 256 threads, t == channel c

    __shared__ float m_s[C_];
    __shared__ float s_s[64];

    const int wbase = b * (NBLK_PER_B * NWARPS);  // 64 warp-partials per batch
    float M = 0.f;
#pragma unroll 8
    for (int k = 0; k < 64; k++)
        M += g_part[(size_t)(wbase + k) * PART_STRIDE + h * C_ + t];

    if (t < 64) s_s[t] = g_part[(size_t)(wbase + t) * PART_STRIDE + 2048 + h];
    __syncthreads();

    float S = 0.f;
#pragma unroll 8
    for (int k = 0; k < 64; k++) S += s_s[k];  // broadcast LDS, identical in all threads

    m_s[t] = M / S;
    __syncthreads();

    if (t < VD_) {
        float acc = bv[h * VD_ + t];
#pragma unroll 8
        for (int c = 0; c < C_; c++)
            acc += m_s[c] * Wv[c * (NH_ * VD_) + h * VD_ + t];
        out[(b * NH_ + h) * VD_ + t] = acc;
    }
}

extern "C" void kernel_launch(void* const* d_in, const int* in_sizes, int n_in,
                              void* d_out, int out_size) {
    const float* kv = (const float*)d_in[0];
    const float* Wk = (const float*)d_in[1];
    // d_in[2] = bk: adds a per-(b,h) constant to scores -> cancels in softmax, unused.
    const float* Wv = (const float*)d_in[3];
    const float* bv = (const float*)d_in[4];
    const float* q  = (const float*)d_in[5];
    float* out = (float*)d_out;

    mha_prep<<<NH_, C_>>>(Wk, q);
    mha_main<<<B_ * NBLK_PER_B, 256>>>(kv);
    mha_combine<<<B_ * NH_, 256>>>(Wv, bv, out);
}

// round 2
// speedup vs baseline: 1.0161x; 1.0161x over previous
#include <cuda_runtime.h>
#include <cstdint>

typedef unsigned long long ull;

#define B_ 16
#define S_ 16384
#define C_ 256
#define NH_ 8
#define VD_ 64
#define NCHUNK 37                       /* chunks per batch; 16*37 = 592 = 4*148 SMs */
#define NCTA (B_ * NCHUNK)              /* 592 */
#define PART_STRIDE 2056                /* 2048 acc + 8 sums */

// Device-global scratch (no runtime allocation allowed).
__device__ __align__(16) float g_wqT[NH_ * C_];                  // wq transposed: [h][c]
__device__ __align__(16) float g_part[(size_t)NCTA * PART_STRIDE];

// ---------------- packed f32x2 helpers ----------------
__device__ __forceinline__ ull f2fma(ull a, ull b, ull c) {
    ull d; asm("fma.rn.f32x2 %0,%1,%2,%3;" : "=l"(d) : "l"(a), "l"(b), "l"(c)); return d;
}
__device__ __forceinline__ ull f2mul(ull a, ull b) {
    ull d; asm("mul.rn.f32x2 %0,%1,%2;" : "=l"(d) : "l"(a), "l"(b)); return d;
}
__device__ __forceinline__ ull f2add(ull a, ull b) {
    ull d; asm("add.rn.f32x2 %0,%1,%2;" : "=l"(d) : "l"(a), "l"(b)); return d;
}
__device__ __forceinline__ ull pk(float x, float y) {
    ull r; asm("mov.b64 %0,{%1,%2};" : "=l"(r) : "f"(x), "f"(y)); return r;
}
__device__ __forceinline__ float2 upk(ull v) {
    float2 r; asm("mov.b64 {%0,%1},%2;" : "=f"(r.x), "=f"(r.y) : "l"(v)); return r;
}
__device__ __forceinline__ ull shx64(ull v, int m) {
    unsigned lo, hi;
    asm("mov.b64 {%0,%1},%2;" : "=r"(lo), "=r"(hi) : "l"(v));
    lo = __shfl_xor_sync(0xffffffffu, lo, m);
    hi = __shfl_xor_sync(0xffffffffu, hi, m);
    ull r; asm("mov.b64 %0,{%1,%2};" : "=l"(r) : "r"(lo), "r"(hi)); return r;
}
__device__ __forceinline__ ull shidx64(ull v, int src) {
    unsigned lo, hi;
    asm("mov.b64 {%0,%1},%2;" : "=r"(lo), "=r"(hi) : "l"(v));
    lo = __shfl_sync(0xffffffffu, lo, src);
    hi = __shfl_sync(0xffffffffu, hi, src);
    ull r; asm("mov.b64 %0,{%1,%2};" : "=l"(r) : "r"(lo), "r"(hi)); return r;
}

// Value-halving warp reduction: 8 packed f32x2 values summed over 32 lanes.
// Afterwards, lane l holds the full-warp sum of value index h(l) = (l>>2)&7.
__device__ __forceinline__ ull reduce8(ull v[8], int lane) {
    {
        bool hi = (lane & 16) != 0;
#pragma unroll
        for (int j = 0; j < 4; j++) {
            ull snd = hi ? v[j] : v[j + 4];
            ull kp  = hi ? v[j + 4] : v[j];
            v[j] = f2add(kp, shx64(snd, 16));
        }
    }
    {
        bool hi = (lane & 8) != 0;
#pragma unroll
        for (int j = 0; j < 2; j++) {
            ull snd = hi ? v[j] : v[j + 2];
            ull kp  = hi ? v[j + 2] : v[j];
            v[j] = f2add(kp, shx64(snd, 8));
        }
    }
    {
        bool hi = (lane & 4) != 0;
        ull snd = hi ? v[0] : v[1];
        ull kp  = hi ? v[1] : v[0];
        v[0] = f2add(kp, shx64(snd, 4));
    }
    v[0] = f2add(v[0], shx64(v[0], 2));
    v[0] = f2add(v[0], shx64(v[0], 1));
    return v[0];
}

// ---------------- Kernel A: fold Wk @ query -> wq[h][c] ----------------
// One warp per (h,c) output; lanes cover the 64-d dot product, coalesced loads.
__global__ void mha_prep(const float* __restrict__ Wk, const float* __restrict__ q) {
    int w = threadIdx.x >> 5, lane = threadIdx.x & 31;
    int idx = blockIdx.x * 32 + w;   // 0..2047 = h*256 + c
    int h = idx >> 8, c = idx & 255;
    float a = Wk[c * 512 + h * 64 + lane]      * q[h * 64 + lane]
            + Wk[c * 512 + h * 64 + lane + 32] * q[h * 64 + lane + 32];
#pragma unroll
    for (int m = 16; m; m >>= 1) a += __shfl_xor_sync(0xffffffffu, a, m);
    if (lane == 0) g_wqT[h * C_ + c] = a;
}

// ---------------- main-kernel helpers ----------------
__device__ __forceinline__ void load2(ull buf[2][4], const float* base, int row, int c0) {
#pragma unroll
    for (int rr = 0; rr < 2; rr++) {
        const float* rowp = base + (size_t)(row + rr) * C_ + c0;
        ulonglong2 a0 = *reinterpret_cast<const ulonglong2*>(rowp);
        ulonglong2 a1 = *reinterpret_cast<const ulonglong2*>(rowp + 4);
        buf[rr][0] = a0.x; buf[rr][1] = a0.y;
        buf[rr][2] = a1.x; buf[rr][3] = a1.y;
    }
}

__device__ __forceinline__ void process2(const ull buf[2][4], const ull wq2[4][NH_],
                                         ull acc2[NH_][4], ull& sum2, int lane) {
    // per-row 8-head score partials (packed over c-pairs), horizontal add
    float s0[NH_], s1[NH_];
    {
        ull p[NH_];
#pragma unroll
        for (int h = 0; h < NH_; h++) p[h] = f2mul(buf[0][0], wq2[0][h]);
#pragma unroll
        for (int j2 = 1; j2 < 4; j2++)
#pragma unroll
            for (int h = 0; h < NH_; h++) p[h] = f2fma(buf[0][j2], wq2[j2][h], p[h]);
#pragma unroll
        for (int h = 0; h < NH_; h++) { float2 t = upk(p[h]); s0[h] = t.x + t.y; }
#pragma unroll
        for (int h = 0; h < NH_; h++) p[h] = f2mul(buf[1][0], wq2[0][h]);
#pragma unroll
        for (int j2 = 1; j2 < 4; j2++)
#pragma unroll
            for (int h = 0; h < NH_; h++) p[h] = f2fma(buf[1][j2], wq2[j2][h], p[h]);
#pragma unroll
        for (int h = 0; h < NH_; h++) { float2 t = upk(p[h]); s1[h] = t.x + t.y; }
    }
    ull v[NH_];
#pragma unroll
    for (int h = 0; h < NH_; h++) v[h] = pk(s0[h], s1[h]);
    ull r0 = reduce8(v, lane);  // lane holds packed (score_row0, score_row1) of head (lane>>2)&7

    float2 e = upk(r0);
    e.x = __expf(e.x); e.y = __expf(e.y);   // scores are O(1): safe without max-sub in fp32
    ull w0 = pk(e.x, e.y);
    sum2 = f2add(sum2, w0);

#pragma unroll
    for (int h = 0; h < NH_; h++) {
        ull wp = shidx64(w0, 4 * h);
        float2 t = upk(wp);
        ull a0 = pk(t.x, t.x), a1 = pk(t.y, t.y);
#pragma unroll
        for (int j2 = 0; j2 < 4; j2++)
            acc2[h][j2] = f2fma(a0, buf[0][j2], f2fma(a1, buf[1][j2], acc2[h][j2]));
    }
}

// ---------------- Kernel B: fused scores + exp + weighted kv accumulation ----------------
__global__ void __launch_bounds__(256, 1) mha_main(const float* __restrict__ kv) {
    const int b  = blockIdx.x / NCHUNK;
    const int ch = blockIdx.x % NCHUNK;
    const int rowStart = ((ch * S_) / NCHUNK) & ~15;
    const int rowEnd   = (ch == NCHUNK - 1) ? S_ : (((ch + 1) * S_) / NCHUNK) & ~15;
    const int iters = (rowEnd - rowStart) >> 4;   // 2 rows/iter, 8 warps

    const int w    = threadIdx.x >> 5;
    const int lane = threadIdx.x & 31;
    const int c0   = lane * 8;

    // loop-invariant packed query-weights: wq2[j2][h] = (wq[c0+2j2][h], wq[c0+2j2+1][h])
    ull wq2[4][NH_];
#pragma unroll
    for (int j2 = 0; j2 < 4; j2++)
#pragma unroll
        for (int h = 0; h < NH_; h++)
            wq2[j2][h] = *reinterpret_cast<const ull*>(g_wqT + h * C_ + c0 + 2 * j2);

    ull acc2[NH_][4];
#pragma unroll
    for (int h = 0; h < NH_; h++)
#pragma unroll
        for (int j2 = 0; j2 < 4; j2++) acc2[h][j2] = 0ull;
    ull sum2 = 0ull;

    const float* base = kv + ((size_t)b * S_ + rowStart) * C_;

    // software-pipelined: prefetch next row-pair while computing current
    ull bufA[2][4], bufB[2][4];
    load2(bufA, base, 2 * w, c0);
    for (int i = 0; i < iters; i += 2) {
        const bool has1 = (i + 1) < iters;
        if (has1) load2(bufB, base, 2 * (w + 8 * (i + 1)), c0);
        process2(bufA, wq2, acc2, sum2, lane);
        if (i + 2 < iters) load2(bufA, base, 2 * (w + 8 * (i + 2)), c0);
        if (has1) process2(bufB, wq2, acc2, sum2, lane);
    }

    // ---- CTA-level merge of 8 warp partials in smem ----
    __shared__ float red[4][2048];
    __shared__ float reds[4][8];
    float2 sv = upk(sum2);
    float mysum = sv.x + sv.y;   // valid at lanes 0,4,..,28 for head lane>>2

    if (w < 4) {
#pragma unroll
        for (int h = 0; h < NH_; h++)
#pragma unroll
            for (int j2 = 0; j2 < 4; j2++)
                *reinterpret_cast<ull*>(&red[w][h * C_ + c0 + 2 * j2]) = acc2[h][j2];
        if ((lane & 3) == 0) reds[w][lane >> 2] = mysum;
    }
    __syncthreads();
    if (w >= 4) {
#pragma unroll
        for (int h = 0; h < NH_; h++)
#pragma unroll
            for (int j2 = 0; j2 < 4; j2++) {
                ull* pp = reinterpret_cast<ull*>(&red[w - 4][h * C_ + c0 + 2 * j2]);
                *pp = f2add(*pp, acc2[h][j2]);
            }
        if ((lane & 3) == 0) reds[w - 4][lane >> 2] += mysum;
    }
    __syncthreads();

    float* dst = g_part + (size_t)blockIdx.x * PART_STRIDE;
    const int t = threadIdx.x;
#pragma unroll
    for (int j2 = 0; j2 < 4; j2++) {
        ull a = *reinterpret_cast<ull*>(&red[0][t * 8 + 2 * j2]);
        a = f2add(a, *reinterpret_cast<ull*>(&red[1][t * 8 + 2 * j2]));
        a = f2add(a, *reinterpret_cast<ull*>(&red[2][t * 8 + 2 * j2]));
        a = f2add(a, *reinterpret_cast<ull*>(&red[3][t * 8 + 2 * j2]));
        *reinterpret_cast<ull*>(dst + t * 8 + 2 * j2) = a;
    }
    if (t < 8) dst[2048 + t] = reds[0][t] + reds[1][t] + reds[2][t] + reds[3][t];
}

// ---------------- Kernel C: merge partials, normalize, project with Wv ----------------
__global__ void mha_combine(const float* __restrict__ Wv, const float* __restrict__ bv,
                            float* __restrict__ out) {
    const int b = blockIdx.x >> 3;
    const int h = blockIdx.x & 7;
    const int t = threadIdx.x;   // 256 threads, t == channel c

    __shared__ float m_s[C_];
    __shared__ float s_s[NCHUNK];

    const size_t base = (size_t)b * NCHUNK * PART_STRIDE;
    float M = 0.f;
#pragma unroll
    for (int k = 0; k < NCHUNK; k++)
        M += g_part[base + (size_t)k * PART_STRIDE + h * C_ + t];

    if (t < NCHUNK) s_s[t] = g_part[base + (size_t)t * PART_STRIDE + 2048 + h];
    __syncthreads();

    float S = 0.f;
#pragma unroll
    for (int k = 0; k < NCHUNK; k++) S += s_s[k];

    m_s[t] = M / S;
    __syncthreads();

    if (t < VD_) {
        float acc = bv[h * VD_ + t];
#pragma unroll 8
        for (int c = 0; c < C_; c++)
            acc += m_s[c] * Wv[c * (NH_ * VD_) + h * VD_ + t];
        out[(b * NH_ + h) * VD_ + t] = acc;
    }
}

extern "C" void kernel_launch(void* const* d_in, const int* in_sizes, int n_in,
                              void* d_out, int out_size) {
    const float* kv = (const float*)d_in[0];
    const float* Wk = (const float*)d_in[1];
    // d_in[2] = bk: per-(b,h) additive constant on scores -> cancels in softmax, unused.
    const float* Wv = (const float*)d_in[3];
    const float* bv = (const float*)d_in[4];
    const float* q  = (const float*)d_in[5];
    float* out = (float*)d_out;

    mha_prep<<<64, 1024>>>(Wk, q);
    mha_main<<<NCTA, 256>>>(kv);
    mha_combine<<<B_ * NH_, 256>>>(Wv, bv, out);
}

// round 3
// speedup vs baseline: 1.1388x; 1.1208x over previous
#include <cuda_runtime.h>
#include <cstdint>

typedef unsigned long long ull;

#define B_ 16
#define S_ 16384
#define C_ 256
#define NH_ 8
#define VD_ 64
#define CHB 18                            /* chunks per batch */
#define NCTA (B_ * CHB)                   /* 288 = ~2 CTAs per SM, one wave */
#define PART_STRIDE 2056                  /* 2048 acc + 8 sums */
#define GROUPS_PER_B 2048                 /* 8-row groups per batch */
#define NSTAGE 4
#define STAGE_ROWS 8
#define STAGE_BYTES (STAGE_ROWS * C_ * 4) /* 8192 */
#define LOG2E 1.4426950408889634f

// Device-global scratch (no runtime allocation allowed).
__device__ __align__(16) float g_wqT[NH_ * C_];                  // (Wk @ q) * log2e, [h][c]
__device__ __align__(16) float g_part[(size_t)NCTA * PART_STRIDE];

// ---------------- packed f32x2 helpers ----------------
__device__ __forceinline__ ull f2fma(ull a, ull b, ull c) {
    ull d; asm("fma.rn.f32x2 %0,%1,%2,%3;" : "=l"(d) : "l"(a), "l"(b), "l"(c)); return d;
}
__device__ __forceinline__ ull f2mul(ull a, ull b) {
    ull d; asm("mul.rn.f32x2 %0,%1,%2;" : "=l"(d) : "l"(a), "l"(b)); return d;
}
__device__ __forceinline__ ull f2add(ull a, ull b) {
    ull d; asm("add.rn.f32x2 %0,%1,%2;" : "=l"(d) : "l"(a), "l"(b)); return d;
}
__device__ __forceinline__ ull pk(float x, float y) {
    ull r; asm("mov.b64 %0,{%1,%2};" : "=l"(r) : "f"(x), "f"(y)); return r;
}
__device__ __forceinline__ float2 upk(ull v) {
    float2 r; asm("mov.b64 {%0,%1},%2;" : "=f"(r.x), "=f"(r.y) : "l"(v)); return r;
}
__device__ __forceinline__ ull shx64(ull v, int m) {
    unsigned lo, hi;
    asm("mov.b64 {%0,%1},%2;" : "=r"(lo), "=r"(hi) : "l"(v));
    lo = __shfl_xor_sync(0xffffffffu, lo, m);
    hi = __shfl_xor_sync(0xffffffffu, hi, m);
    ull r; asm("mov.b64 %0,{%1,%2};" : "=l"(r) : "r"(lo), "r"(hi)); return r;
}

__device__ __forceinline__ uint32_t smem_u32(const void* p) {
    uint32_t a;
    asm("{ .reg .u64 t; cvta.to.shared.u64 t, %1; cvt.u32.u64 %0, t; }" : "=r"(a) : "l"(p));
    return a;
}

// ---------------- mbarrier / bulk-copy primitives ----------------
#define MBARRIER_INIT(mbar, cnt) \
    asm volatile("mbarrier.init.shared.b64 [%0], %1;" :: "r"(mbar), "r"((uint32_t)(cnt)) : "memory")
#define MBARRIER_ARRIVE(mbar) \
    asm volatile("mbarrier.arrive.shared.b64 _, [%0];" :: "r"(mbar) : "memory")
#define MBARRIER_EXPECT_TX(mbar, bytes) \
    asm volatile("mbarrier.arrive.expect_tx.shared.b64 _, [%0], %1;" :: "r"(mbar), "r"((uint32_t)(bytes)) : "memory")

#define MBARRIER_WAIT_PARITY(mbar, par) do {                                            \
    uint32_t _m = (mbar), _p = (uint32_t)(par), _done;                                  \
    asm volatile("{\n\t.reg .pred p;\n\t"                                               \
        "mbarrier.try_wait.parity.acquire.cta.shared::cta.b64 p, [%1], %2;\n\t"         \
        "selp.b32 %0, 1, 0, p;\n\t}"                                                    \
        : "=r"(_done) : "r"(_m), "r"(_p) : "memory");                                   \
    if (!_done) {                                                                       \
        asm volatile("{\n\t.reg .pred P1;\n\t"                                          \
            "WL_%=:\n\t"                                                                \
            "mbarrier.try_wait.parity.acquire.cta.shared::cta.b64 P1, [%0], %1, 0x989680;\n\t" \
            "@P1 bra.uni WD_%=;\n\t"                                                    \
            "bra.uni WL_%=;\n\t"                                                        \
            "WD_%=:\n\t}"                                                               \
            :: "r"(_m), "r"(_p) : "memory");                                            \
    }                                                                                   \
} while (0)

#define MBARRIER_WAIT_PARITY_RELAXED(mbar, par) do {                                    \
    uint32_t _m = (mbar), _p = (uint32_t)(par), _done;                                  \
    asm volatile("{\n\t.reg .pred p;\n\t"                                               \
        "mbarrier.try_wait.parity.relaxed.cta.shared::cta.b64 p, [%1], %2, 0x989680;\n\t" \
        "selp.b32 %0, 1, 0, p;\n\t}"                                                    \
        : "=r"(_done) : "r"(_m), "r"(_p) : "memory");                                   \
    if (!_done) {                                                                       \
        asm volatile("{\n\t.reg .pred P1;\n\t"                                          \
            "WL_%=:\n\t"                                                                \
            "mbarrier.try_wait.parity.relaxed.cta.shared::cta.b64 P1, [%0], %1, 0x989680;\n\t" \
            "@P1 bra.uni WD_%=;\n\t"                                                    \
            "bra.uni WL_%=;\n\t"                                                        \
            "WD_%=:\n\t}"                                                               \
            :: "r"(_m), "r"(_p) : "memory");                                            \
    }                                                                                   \
} while (0)

#define BULK_G2S(dst_u32, src_ptr, bytes, mbar) \
    asm volatile("cp.async.bulk.shared::cluster.global.mbarrier::complete_tx::bytes [%0], [%1], %2, [%3];" \
        :: "r"(dst_u32), "l"(src_ptr), "r"((uint32_t)(bytes)), "r"(mbar) : "memory")

// Value-halving warp reduction: 8 packed f32x2 values summed over 32 lanes.
// Afterwards, lane l holds the full-warp sum of value index h(l) = (l>>2)&7.
__device__ __forceinline__ ull reduce8(ull v[8], int lane) {
    {
        bool hi = (lane & 16) != 0;
#pragma unroll
        for (int j = 0; j < 4; j++) {
            ull snd = hi ? v[j] : v[j + 4];
            ull kp  = hi ? v[j + 4] : v[j];
            v[j] = f2add(kp, shx64(snd, 16));
        }
    }
    {
        bool hi = (lane & 8) != 0;
#pragma unroll
        for (int j = 0; j < 2; j++) {
            ull snd = hi ? v[j] : v[j + 2];
            ull kp  = hi ? v[j + 2] : v[j];
            v[j] = f2add(kp, shx64(snd, 8));
        }
    }
    {
        bool hi = (lane & 4) != 0;
        ull snd = hi ? v[0] : v[1];
        ull kp  = hi ? v[1] : v[0];
        v[0] = f2add(kp, shx64(snd, 4));
    }
    v[0] = f2add(v[0], shx64(v[0], 2));
    v[0] = f2add(v[0], shx64(v[0], 1));
    return v[0];
}

// ---------------- Kernel A (x2): fold Wk @ q -> wq[h][c], scaled by log2e ----------------
// One warp per (h,c) output; two launches (hbase 0 and 4) so the launch period is 4.
__global__ void mha_prep(const float* __restrict__ Wk, const float* __restrict__ q, int hbase) {
    int w = threadIdx.x >> 5, lane = threadIdx.x & 31;
    int idx = blockIdx.x * 32 + w;            // 0..1023 = (h - hbase)*256 + c
    int h = hbase + (idx >> 8), c = idx & 255;
    float a = Wk[c * 512 + h * 64 + lane]      * q[h * 64 + lane]
            + Wk[c * 512 + h * 64 + lane + 32] * q[h * 64 + lane + 32];
#pragma unroll
    for (int m = 16; m; m >>= 1) a += __shfl_xor_sync(0xffffffffu, a, m);
    if (lane == 0) g_wqT[h * C_ + c] = a * LOG2E;
}

// ---------------- Kernel B: warp-specialized fused softmax-pool ----------------
// 4 score warps (w0-3) + 4 acc warps (w4-7); bulk-copy ring of 4 x 8-row stages.
__global__ void __launch_bounds__(256, 2) mha_main(const float* __restrict__ kv) {
    __shared__ __align__(128) char sm_rows[NSTAGE * STAGE_BYTES];   // 32KB; reused as merge area
    __shared__ __align__(16) ull sm_w[NSTAGE][4][NH_];              // per-stage pair weights (packed rows)
    __shared__ __align__(16) ull sm_mbar[3 * NSTAGE];               // full | wsync | empty
    __shared__ float sm_reds[4][NH_];

    const int tid  = threadIdx.x;
    const int w    = tid >> 5;
    const int lane = tid & 31;
    const int b  = blockIdx.x / CHB;
    const int ch = blockIdx.x % CHB;
    const int gstart = (ch * GROUPS_PER_B) / CHB;
    const int gend   = ((ch + 1) * GROUPS_PER_B) / CHB;
    const int ntiles = gend - gstart;
    const int c0 = lane * 8;

    const uint32_t mb_full = smem_u32(&sm_mbar[0]);
    const uint32_t mb_ws   = smem_u32(&sm_mbar[NSTAGE]);
    const uint32_t mb_emp  = smem_u32(&sm_mbar[2 * NSTAGE]);
    const uint32_t rows_u32 = smem_u32(sm_rows);

    if (tid == 0) {
#pragma unroll
        for (int s = 0; s < NSTAGE; s++) {
            MBARRIER_INIT(mb_full + 8u * s, 1);
            MBARRIER_INIT(mb_ws   + 8u * s, 128);
            MBARRIER_INIT(mb_emp  + 8u * s, 128);
        }
    }
    __syncthreads();

    const float* src = kv + ((size_t)b * S_ + (size_t)gstart * STAGE_ROWS) * C_;

    // prologue: 2 stages in flight
    if (tid == 0) {
#pragma unroll
        for (int u = 0; u < 2; u++) {
            if (u < ntiles) {
                MBARRIER_EXPECT_TX(mb_full + 8u * u, STAGE_BYTES);
                BULK_G2S(rows_u32 + u * STAGE_BYTES, src + (size_t)u * STAGE_ROWS * C_,
                         STAGE_BYTES, mb_full + 8u * u);
            }
        }
    }

    ull acc2[NH_][4];
#pragma unroll
    for (int h = 0; h < NH_; h++)
#pragma unroll
        for (int j2 = 0; j2 < 4; j2++) acc2[h][j2] = 0ull;
    float mysum = 0.f;

    if (w < 4) {
        // ================= score warps =================
        ull wq2[4][NH_];
#pragma unroll
        for (int j2 = 0; j2 < 4; j2++)
#pragma unroll
            for (int h = 0; h < NH_; h++)
                wq2[j2][h] = *reinterpret_cast<const ull*>(g_wqT + h * C_ + c0 + 2 * j2);

        ull sum2 = 0ull;
        for (int t = 0; t < ntiles; t++) {
            const int slot = t & 3;
            const int fp   = (t >> 2) & 1;

            if (tid == 0) {
                const int u = t + 2;
                if (u < ntiles) {
                    const int us = u & 3;
                    if (u >= NSTAGE) MBARRIER_WAIT_PARITY_RELAXED(mb_emp + 8u * us, ((u >> 2) - 1) & 1);
                    MBARRIER_EXPECT_TX(mb_full + 8u * us, STAGE_BYTES);
                    BULK_G2S(rows_u32 + us * STAGE_BYTES, src + (size_t)u * STAGE_ROWS * C_,
                             STAGE_BYTES, mb_full + 8u * us);
                }
            }
            MBARRIER_WAIT_PARITY(mb_full + 8u * slot, fp);

            const char* rbase = sm_rows + slot * STAGE_BYTES;
            ull kv0[4], kv1[4];
            {
                ulonglong2 a0 = *reinterpret_cast<const ulonglong2*>(rbase + (2 * w) * 1024 + lane * 32);
                ulonglong2 a1 = *reinterpret_cast<const ulonglong2*>(rbase + (2 * w) * 1024 + lane * 32 + 16);
                kv0[0] = a0.x; kv0[1] = a0.y; kv0[2] = a1.x; kv0[3] = a1.y;
                ulonglong2 b0 = *reinterpret_cast<const ulonglong2*>(rbase + (2 * w + 1) * 1024 + lane * 32);
                ulonglong2 b1 = *reinterpret_cast<const ulonglong2*>(rbase + (2 * w + 1) * 1024 + lane * 32 + 16);
                kv1[0] = b0.x; kv1[1] = b0.y; kv1[2] = b1.x; kv1[3] = b1.y;
            }

            float s0[NH_];
            ull p[NH_];
#pragma unroll
            for (int h = 0; h < NH_; h++) p[h] = f2mul(kv0[0], wq2[0][h]);
#pragma unroll
            for (int j2 = 1; j2 < 4; j2++)
#pragma unroll
                for (int h = 0; h < NH_; h++) p[h] = f2fma(kv0[j2], wq2[j2][h], p[h]);
#pragma unroll
            for (int h = 0; h < NH_; h++) { float2 u2 = upk(p[h]); s0[h] = u2.x + u2.y; }
#pragma unroll
            for (int h = 0; h < NH_; h++) p[h] = f2mul(kv1[0], wq2[0][h]);
#pragma unroll
            for (int j2 = 1; j2 < 4; j2++)
#pragma unroll
                for (int h = 0; h < NH_; h++) p[h] = f2fma(kv1[j2], wq2[j2][h], p[h]);

            ull v[NH_];
#pragma unroll
            for (int h = 0; h < NH_; h++) { float2 u2 = upk(p[h]); v[h] = pk(s0[h], u2.x + u2.y); }

            ull r0 = reduce8(v, lane);   // lanes 4h..4h+3: packed (score_row0, score_row1) of head h
            float2 e = upk(r0);
            asm("ex2.approx.f32 %0, %0;" : "+f"(e.x));
            asm("ex2.approx.f32 %0, %0;" : "+f"(e.y));
            ull wgt = pk(e.x, e.y);
            sum2 = f2add(sum2, wgt);

            if ((lane & 3) == 0) sm_w[slot][w][lane >> 2] = wgt;
            MBARRIER_ARRIVE(mb_ws + 8u * slot);
        }
        float2 sv = upk(sum2);
        mysum = sv.x + sv.y;
    } else {
        // ================= acc warps =================
        const int wa = w - 4;
        for (int t = 0; t < ntiles; t++) {
            const int slot = t & 3;
            const int fp   = (t >> 2) & 1;
            MBARRIER_WAIT_PARITY(mb_ws + 8u * slot, fp);

            const char* rbase = sm_rows + slot * STAGE_BYTES;
            ull kv0[4], kv1[4];
            {
                ulonglong2 a0 = *reinterpret_cast<const ulonglong2*>(rbase + (2 * wa) * 1024 + lane * 32);
                ulonglong2 a1 = *reinterpret_cast<const ulonglong2*>(rbase + (2 * wa) * 1024 + lane * 32 + 16);
                kv0[0] = a0.x; kv0[1] = a0.y; kv0[2] = a1.x; kv0[3] = a1.y;
                ulonglong2 b0 = *reinterpret_cast<const ulonglong2*>(rbase + (2 * wa + 1) * 1024 + lane * 32);
                ulonglong2 b1 = *reinterpret_cast<const ulonglong2*>(rbase + (2 * wa + 1) * 1024 + lane * 32 + 16);
                kv1[0] = b0.x; kv1[1] = b0.y; kv1[2] = b1.x; kv1[3] = b1.y;
            }

#pragma unroll
            for (int h = 0; h < NH_; h++) {
                ull wll = sm_w[slot][wa][h];
                float2 e = upk(wll);
                ull a0 = pk(e.x, e.x), a1 = pk(e.y, e.y);
#pragma unroll
                for (int j2 = 0; j2 < 4; j2++)
                    acc2[h][j2] = f2fma(a0, kv0[j2], f2fma(a1, kv1[j2], acc2[h][j2]));
            }
            MBARRIER_ARRIVE(mb_emp + 8u * slot);
        }
    }

    __syncthreads();   // pipeline drained; stage smem reusable as merge area

    float* red = reinterpret_cast<float*>(sm_rows);   // [4][2048]
    if (w >= 4) {
        const int wa = w - 4;
#pragma unroll
        for (int h = 0; h < NH_; h++)
#pragma unroll
            for (int j2 = 0; j2 < 4; j2++)
                *reinterpret_cast<ull*>(&red[wa * 2048 + h * C_ + c0 + 2 * j2]) = acc2[h][j2];
    } else {
        if ((lane & 3) == 0) sm_reds[w][lane >> 2] = mysum;
    }
    __syncthreads();

    float* dst = g_part + (size_t)blockIdx.x * PART_STRIDE;
#pragma unroll
    for (int j2 = 0; j2 < 4; j2++) {
        ull a = *reinterpret_cast<ull*>(&red[tid * 8 + 2 * j2]);
        a = f2add(a, *reinterpret_cast<ull*>(&red[2048 + tid * 8 + 2 * j2]));
        a = f2add(a, *reinterpret_cast<ull*>(&red[4096 + tid * 8 + 2 * j2]));
        a = f2add(a, *reinterpret_cast<ull*>(&red[6144 + tid * 8 + 2 * j2]));
        *reinterpret_cast<ull*>(dst + tid * 8 + 2 * j2) = a;
    }
    if (tid < 8) dst[2048 + tid] = sm_reds[0][tid] + sm_reds[1][tid] + sm_reds[2][tid] + sm_reds[3][tid];
}

// ---------------- Kernel C: merge partials, normalize, project with Wv ----------------
__global__ void mha_combine(const float* __restrict__ Wv, const float* __restrict__ bv,
                            float* __restrict__ out) {
    const int b = blockIdx.x >> 3;
    const int h = blockIdx.x & 7;
    const int t = threadIdx.x;   // 256 threads, t == channel c

    __shared__ float m_s[C_];
    __shared__ float s_s[CHB];

    const size_t base = (size_t)b * CHB * PART_STRIDE;
    float M = 0.f;
#pragma unroll
    for (int k = 0; k < CHB; k++)
        M += g_part[base + (size_t)k * PART_STRIDE + h * C_ + t];

    if (t < CHB) s_s[t] = g_part[base + (size_t)t * PART_STRIDE + 2048 + h];
    __syncthreads();

    float S = 0.f;
#pragma unroll
    for (int k = 0; k < CHB; k++) S += s_s[k];

    m_s[t] = M / S;
    __syncthreads();

    if (t < VD_) {
        float acc = bv[h * VD_ + t];
#pragma unroll 8
        for (int c = 0; c < C_; c++)
            acc += m_s[c] * Wv[c * (NH_ * VD_) + h * VD_ + t];
        out[(b * NH_ + h) * VD_ + t] = acc;
    }
}

extern "C" void kernel_launch(void* const* d_in, const int* in_sizes, int n_in,
                              void* d_out, int out_size) {
    const float* kv = (const float*)d_in[0];
    const float* Wk = (const float*)d_in[1];
    // d_in[2] = bk: per-(b,h) additive constant on scores -> cancels in softmax, unused.
    const float* Wv = (const float*)d_in[3];
    const float* bv = (const float*)d_in[4];
    const float* q  = (const float*)d_in[5];
    float* out = (float*)d_out;

    mha_prep<<<32, 1024>>>(Wk, q, 0);
    mha_prep<<<32, 1024>>>(Wk, q, 4);
    mha_main<<<NCTA, 256>>>(kv);
    mha_combine<<<B_ * NH_, 256>>>(Wv, bv, out);
}